// round 1
// baseline (speedup 1.0000x reference)
#include <cuda_runtime.h>

#define Nn 50000
#define Ee 1600000
#define Hh 128
#define Ff 64
#define Gg 50
#define Ll 3
#define NGg 256
#define BINS 16384

#define CUTOFF 10.0f
#define STEP_  (CUTOFF / (Gg - 1))
#define COEFF_ (-0.5f / (STEP_ * STEP_))
#define TABMAX 8.6700f
#define HSTEP  (TABMAX / (BINS - 1))
#define INVH   ((BINS - 1) / TABMAX)
#define LN2    0.69314718055994531f
#define PI_F   3.14159265358979f

// ---------------- scratch (static device memory; no allocation) ----------------
__device__ __align__(16) float g_h[Nn * Hh];      // node features
__device__ __align__(16) float g_t1[Nn * Ff];     // h @ l1w   (also reused for output MLP hidden)
__device__ __align__(16) float g_agg[Nn * Ff];    // segment-sum accumulator
__device__ __align__(16) float g_x[Nn * Hh];      // intermediate node features
__device__ __align__(16) float g_tab[(size_t)Ll * BINS * Ff];  // W(d) lookup tables
__device__ int   g_eb[Ee];                         // per-edge table bin
__device__ float g_u[Ee];                          // C*(1-frac)
__device__ float g_v[Ee];                          // C*frac

__device__ __forceinline__ float sspf(float x) {
    float sp = (x > 20.0f) ? x : log1pf(__expf(x));
    return sp - LN2;
}

// ---------------- h init: gather embedding rows ----------------
__global__ void init_h(const int* __restrict__ z, const float* __restrict__ emb) {
    int i = blockIdx.x * 256 + threadIdx.x;     // i < Nn*32 (exact)
    int n = i >> 5, c = i & 31;
    ((float4*)g_h)[i] = ((const float4*)emb)[(size_t)__ldg(z + n) * 32 + c];
}

// ---------------- per-edge preprocessing: distance -> (bin, u, v) ----------------
__global__ void edge_prep(const float* __restrict__ pos, const int* __restrict__ ei) {
    int e = blockIdx.x * 256 + threadIdx.x;
    if (e >= Ee) return;
    int s = __ldg(ei + e);
    int t = __ldg(ei + Ee + e);
    float dx = __ldg(pos + s * 3 + 0) - __ldg(pos + t * 3 + 0);
    float dy = __ldg(pos + s * 3 + 1) - __ldg(pos + t * 3 + 1);
    float dz = __ldg(pos + s * 3 + 2) - __ldg(pos + t * 3 + 2);
    float d = sqrtf(dx * dx + dy * dy + dz * dz);
    float C = 0.5f * (cosf(d * (PI_F / CUTOFF)) + 1.0f);
    float tt = d * INVH;
    int b = (int)tt;
    if (b > BINS - 2) b = BINS - 2;
    float fr = tt - (float)b;
    g_eb[e] = b;
    g_u[e] = C * (1.0f - fr);
    g_v[e] = C * fr;
}

// ---------------- build W(d) tables: W = ssp(gauss(d)@mw1+mb1)@mw2+mb2 ----------------
__global__ __launch_bounds__(256) void build_tab(
    const float* __restrict__ mw1, const float* __restrict__ mb1,
    const float* __restrict__ mw2, const float* __restrict__ mb2)
{
    __shared__ float sW1[Gg * Ff];
    __shared__ float sW2[Ff * Ff];
    __shared__ float sg[4][Gg];
    __shared__ float sa[4][Ff];
    int li = blockIdx.y;
    int tid = threadIdx.x;
    for (int j = tid; j < Gg * Ff; j += 256) sW1[j] = mw1[li * Gg * Ff + j];
    for (int j = tid; j < Ff * Ff; j += 256) sW2[j] = mw2[li * Ff * Ff + j];
    int sub = tid >> 6, f = tid & 63;
    float b1 = __ldg(mb1 + li * Ff + f);
    float b2 = __ldg(mb2 + li * Ff + f);
    __syncthreads();
    for (int c = 0; c < 16; c++) {
        int bin = blockIdx.x * 64 + c * 4 + sub;
        float d = bin * HSTEP;
        if (f < Gg) { float dd = d - f * STEP_; sg[sub][f] = __expf(COEFF_ * dd * dd); }
        __syncthreads();
        float a = b1;
        #pragma unroll
        for (int g = 0; g < Gg; g++) a += sg[sub][g] * sW1[g * Ff + f];
        sa[sub][f] = sspf(a);
        __syncthreads();
        float w = b2;
        #pragma unroll 8
        for (int k = 0; k < Ff; k++) w += sa[sub][k] * sW2[k * Ff + f];
        g_tab[((size_t)li * BINS + bin) * Ff + f] = w;
        __syncthreads();
    }
}

// ---------------- generic node GEMM (128x64 tile, 8x4 microtile, XOR-swizzled A) ----
// MODE 0: g_t1 = g_h @ W            (K=128, NC=64,  no bias, no act)
// MODE 1: g_x  = ssp(g_agg @ W + b) (K=64,  NC=128)
// MODE 2: g_h += g_x @ W + b        (K=128, NC=128)
// MODE 3: g_t1 = ssp(g_h @ W + b)   (K=128, NC=64)   [output MLP layer 1]
template <int MODE>
__global__ __launch_bounds__(256) void gemm_node(const float* __restrict__ W,
                                                 const float* __restrict__ bias)
{
    constexpr int K  = (MODE == 1) ? 64 : 128;
    constexpr int NC = (MODE == 0 || MODE == 3) ? 64 : 128;
    const float* __restrict__ A = (MODE == 0 || MODE == 3) ? g_h : (MODE == 1) ? g_agg : g_x;
    float* __restrict__ out = (MODE == 0 || MODE == 3) ? g_t1 : (MODE == 1) ? g_x : g_h;

    __shared__ float s_a[128 * 64];
    __shared__ float s_b[64 * 64];
    int tid = threadIdx.x;
    int tx = tid & 15, ty = tid >> 4;
    int rowBase = blockIdx.x * 128;
    int colBase = blockIdx.y * 64;
    float acc[8][4];
    #pragma unroll
    for (int r = 0; r < 8; r++)
        #pragma unroll
        for (int c = 0; c < 4; c++) acc[r][c] = 0.0f;

    for (int kc = 0; kc < K; kc += 64) {
        #pragma unroll
        for (int p = 0; p < 8; p++) {
            int row = p * 16 + ty;
            int rg = rowBase + row;
            float4 v = make_float4(0.f, 0.f, 0.f, 0.f);
            if (rg < Nn) v = *(const float4*)&A[(size_t)rg * K + kc + tx * 4];
            *(float4*)&s_a[row * 64 + ((tx ^ (row & 15)) << 2)] = v;
        }
        #pragma unroll
        for (int p = 0; p < 4; p++) {
            int kr = p * 16 + ty;
            *(float4*)&s_b[kr * 64 + tx * 4] =
                *(const float4*)&W[(size_t)(kc + kr) * NC + colBase + tx * 4];
        }
        __syncthreads();
        #pragma unroll 4
        for (int k4 = 0; k4 < 16; k4++) {
            float4 b0 = *(const float4*)&s_b[(k4 * 4 + 0) * 64 + tx * 4];
            float4 b1 = *(const float4*)&s_b[(k4 * 4 + 1) * 64 + tx * 4];
            float4 b2 = *(const float4*)&s_b[(k4 * 4 + 2) * 64 + tx * 4];
            float4 b3 = *(const float4*)&s_b[(k4 * 4 + 3) * 64 + tx * 4];
            #pragma unroll
            for (int r = 0; r < 8; r++) {
                int row = ty * 8 + r;
                float4 a = *(const float4*)&s_a[row * 64 + ((k4 ^ (row & 15)) << 2)];
                acc[r][0] += a.x * b0.x; acc[r][0] += a.y * b1.x;
                acc[r][0] += a.z * b2.x; acc[r][0] += a.w * b3.x;
                acc[r][1] += a.x * b0.y; acc[r][1] += a.y * b1.y;
                acc[r][1] += a.z * b2.y; acc[r][1] += a.w * b3.y;
                acc[r][2] += a.x * b0.z; acc[r][2] += a.y * b1.z;
                acc[r][2] += a.z * b2.z; acc[r][2] += a.w * b3.z;
                acc[r][3] += a.x * b0.w; acc[r][3] += a.y * b1.w;
                acc[r][3] += a.z * b2.w; acc[r][3] += a.w * b3.w;
            }
        }
        __syncthreads();
    }
    #pragma unroll
    for (int r = 0; r < 8; r++) {
        int rg = rowBase + ty * 8 + r;
        if (rg >= Nn) continue;
        int cg = colBase + tx * 4;
        float4 o = make_float4(acc[r][0], acc[r][1], acc[r][2], acc[r][3]);
        if (MODE != 0) {
            o.x += __ldg(bias + cg + 0); o.y += __ldg(bias + cg + 1);
            o.z += __ldg(bias + cg + 2); o.w += __ldg(bias + cg + 3);
        }
        if (MODE == 1 || MODE == 3) {
            o.x = sspf(o.x); o.y = sspf(o.y); o.z = sspf(o.z); o.w = sspf(o.w);
        }
        float* dst = &out[(size_t)rg * NC + cg];
        if (MODE == 2) {
            float4 cur = *(float4*)dst;
            o.x += cur.x; o.y += cur.y; o.z += cur.z; o.w += cur.w;
        }
        *(float4*)dst = o;
    }
}

// ---------------- zero kernels ----------------
__global__ void zero_agg() {
    int i = blockIdx.x * 256 + threadIdx.x;     // < Nn*Ff/4 (exact)
    ((float4*)g_agg)[i] = make_float4(0.f, 0.f, 0.f, 0.f);
}
__global__ void zero_out(float* out) {
    if (threadIdx.x < NGg) out[threadIdx.x] = 0.0f;
}

// ---------------- edge message + scatter-add (4 threads per edge) ----------------
__global__ __launch_bounds__(256) void edge_msg(const int* __restrict__ ei, int layer) {
    int idx = blockIdx.x * 256 + threadIdx.x;   // < Ee*4 (exact)
    int e = idx >> 2;
    int q = idx & 3;
    int src = __ldg(ei + e);
    int dst = __ldg(ei + Ee + e);
    int b = g_eb[e];
    float u = g_u[e], v = g_v[e];
    const float4* T0 = (const float4*)(g_tab + ((size_t)layer * BINS + b) * Ff) + q * 4;
    const float4* X  = (const float4*)(g_t1 + (size_t)src * Ff) + q * 4;
    float* Ag = g_agg + (size_t)dst * Ff + q * 16;
    #pragma unroll
    for (int j = 0; j < 4; j++) {
        float4 t0 = __ldg(T0 + j);
        float4 t1v = __ldg(T0 + 16 + j);   // next bin row (64 floats = 16 float4)
        float4 x  = __ldg(X + j);
        atomicAdd(Ag + j * 4 + 0, (u * t0.x + v * t1v.x) * x.x);
        atomicAdd(Ag + j * 4 + 1, (u * t0.y + v * t1v.y) * x.y);
        atomicAdd(Ag + j * 4 + 2, (u * t0.z + v * t1v.z) * x.z);
        atomicAdd(Ag + j * 4 + 3, (u * t0.w + v * t1v.w) * x.w);
    }
}

// ---------------- readout: y[n] = hv . ow2 + ob2, scatter into graphs ----------------
__global__ void reduce_out(const int* __restrict__ batch, const float* __restrict__ ow2,
                           const float* __restrict__ ob2, float* __restrict__ out)
{
    int n = blockIdx.x * 256 + threadIdx.x;
    if (n >= Nn) return;
    const float4* hv = (const float4*)(g_t1 + (size_t)n * Ff);
    float s = 0.0f;
    #pragma unroll
    for (int j = 0; j < 16; j++) {
        float4 a = __ldg(hv + j);
        float4 w = __ldg((const float4*)ow2 + j);
        s += a.x * w.x + a.y * w.y + a.z * w.z + a.w * w.w;
    }
    atomicAdd(&out[__ldg(batch + n)], s + __ldg(ob2));
}

// ---------------- host ----------------
extern "C" void kernel_launch(void* const* d_in, const int* in_sizes, int n_in,
                              void* d_out, int out_size)
{
    const int*   z    = (const int*)  d_in[0];
    const float* pos  = (const float*)d_in[1];
    const int*   batch= (const int*)  d_in[2];
    const int*   ei   = (const int*)  d_in[3];
    const float* emb  = (const float*)d_in[4];
    const float* mw1  = (const float*)d_in[5];
    const float* mb1  = (const float*)d_in[6];
    const float* mw2  = (const float*)d_in[7];
    const float* mb2  = (const float*)d_in[8];
    const float* l1w  = (const float*)d_in[9];
    const float* l2w  = (const float*)d_in[10];
    const float* l2b  = (const float*)d_in[11];
    const float* lw   = (const float*)d_in[12];
    const float* lb   = (const float*)d_in[13];
    const float* ow1  = (const float*)d_in[14];
    const float* ob1  = (const float*)d_in[15];
    const float* ow2  = (const float*)d_in[16];
    const float* ob2  = (const float*)d_in[17];
    float* out = (float*)d_out;

    init_h<<<Nn * Hh / 4 / 256, 256>>>(z, emb);                  // 6250 blocks
    edge_prep<<<(Ee + 255) / 256, 256>>>(pos, ei);
    build_tab<<<dim3(BINS / 64, Ll), 256>>>(mw1, mb1, mw2, mb2);

    const int NB = (Nn + 127) / 128;                             // 391
    for (int i = 0; i < Ll; i++) {
        gemm_node<0><<<dim3(NB, 1), 256>>>(l1w + i * Hh * Ff, nullptr);
        zero_agg<<<Nn * Ff / 4 / 256, 256>>>();
        edge_msg<<<Ee * 4 / 256, 256>>>(ei, i);
        gemm_node<1><<<dim3(NB, 2), 256>>>(l2w + i * Ff * Hh, l2b + i * Hh);
        gemm_node<2><<<dim3(NB, 2), 256>>>(lw + i * Hh * Hh, lb + i * Hh);
    }
    zero_out<<<1, 256>>>(out);
    gemm_node<3><<<dim3(NB, 1), 256>>>(ow1, ob1);
    reduce_out<<<(Nn + 255) / 256, 256>>>(batch, ow2, ob2, out);
}

// round 2
// speedup vs baseline: 2.5066x; 2.5066x over previous
#include <cuda_runtime.h>

#define Nn 50000
#define Ee 1600000
#define Hh 128
#define Ff 64
#define Gg 50
#define Ll 3
#define NGg 256
#define BINS 16384

#define CUTOFF 10.0f
#define STEP_  (CUTOFF / (Gg - 1))
#define COEFF_ (-0.5f / (STEP_ * STEP_))
#define TABMAX 8.6700f
#define HSTEP  (TABMAX / (BINS - 1))
#define INVH   ((BINS - 1) / TABMAX)
#define LN2    0.69314718055994531f
#define PI_F   3.14159265358979f

// ---------------- scratch (static device memory; no allocation) ----------------
__device__ __align__(16) float g_h[Nn * Hh];      // node features
__device__ __align__(16) float g_t1[Nn * Ff];     // h @ l1w (also output-MLP hidden)
__device__ __align__(16) float g_agg[Nn * Ff];    // segment-sum result
__device__ __align__(16) float g_x[Nn * Hh];      // intermediate node features
__device__ __align__(16) float g_tab[(size_t)Ll * BINS * Ff];  // W(d) lookup tables
__device__ __align__(16) int4 g_cs[Ee];           // CSR-ordered edges: {src, bin, u, v}
__device__ int g_cnt[Nn];                          // dst histogram
__device__ int g_rowptr[Nn + 1];
__device__ int g_cur[Nn];                          // fill cursors

__device__ __forceinline__ float sspf(float x) {
    float sp = (x > 20.0f) ? x : log1pf(__expf(x));
    return sp - LN2;
}

// ---------------- h init: gather embedding rows ----------------
__global__ void init_h(const int* __restrict__ z, const float* __restrict__ emb) {
    int i = blockIdx.x * 256 + threadIdx.x;     // i < Nn*32 (exact)
    int n = i >> 5, c = i & 31;
    ((float4*)g_h)[i] = ((const float4*)emb)[(size_t)__ldg(z + n) * 32 + c];
}

// ---------------- CSR build ----------------
__global__ void zero_cnt() {
    int i = blockIdx.x * 256 + threadIdx.x;
    if (i < Nn) g_cnt[i] = 0;
}
__global__ void count_dst(const int* __restrict__ ei) {
    int e = blockIdx.x * 256 + threadIdx.x;
    if (e < Ee) atomicAdd(&g_cnt[__ldg(ei + Ee + e)], 1);
}
// single-block exclusive scan over Nn counts -> rowptr, cur
__global__ __launch_bounds__(1024) void scan_counts() {
    __shared__ int sp[1024];
    const int CH = (Nn + 1023) / 1024;              // 49
    int t = threadIdx.x;
    int base = t * CH;
    int s = 0;
    for (int i = 0; i < CH; i++) {
        int idx = base + i;
        if (idx < Nn) s += g_cnt[idx];
    }
    sp[t] = s;
    __syncthreads();
    // Hillis-Steele inclusive scan
    for (int off = 1; off < 1024; off <<= 1) {
        int v = (t >= off) ? sp[t - off] : 0;
        __syncthreads();
        sp[t] += v;
        __syncthreads();
    }
    int run = (t == 0) ? 0 : sp[t - 1];             // exclusive prefix
    for (int i = 0; i < CH; i++) {
        int idx = base + i;
        if (idx < Nn) {
            g_rowptr[idx] = run;
            g_cur[idx] = run;
            run += g_cnt[idx];
        }
    }
    if (t == 1023) g_rowptr[Nn] = sp[1023];
}

// ---------------- fused edge prep + CSR fill ----------------
__global__ void edge_prep_fill(const float* __restrict__ pos, const int* __restrict__ ei) {
    int e = blockIdx.x * 256 + threadIdx.x;
    if (e >= Ee) return;
    int s = __ldg(ei + e);
    int t = __ldg(ei + Ee + e);
    float dx = __ldg(pos + s * 3 + 0) - __ldg(pos + t * 3 + 0);
    float dy = __ldg(pos + s * 3 + 1) - __ldg(pos + t * 3 + 1);
    float dz = __ldg(pos + s * 3 + 2) - __ldg(pos + t * 3 + 2);
    float d = sqrtf(dx * dx + dy * dy + dz * dz);
    float C = 0.5f * (cosf(d * (PI_F / CUTOFF)) + 1.0f);
    float tt = d * INVH;
    int b = (int)tt;
    if (b > BINS - 2) b = BINS - 2;
    float fr = tt - (float)b;
    float u = C * (1.0f - fr);
    float v = C * fr;
    int p = atomicAdd(&g_cur[t], 1);
    g_cs[p] = make_int4(s, b, __float_as_int(u), __float_as_int(v));
}

// ---------------- build W(d) tables: W = ssp(gauss(d)@mw1+mb1)@mw2+mb2 ----------------
__global__ __launch_bounds__(256) void build_tab(
    const float* __restrict__ mw1, const float* __restrict__ mb1,
    const float* __restrict__ mw2, const float* __restrict__ mb2)
{
    __shared__ float sW1[Gg * Ff];
    __shared__ float sW2[Ff * Ff];
    __shared__ float sg[4][Gg];
    __shared__ float sa[4][Ff];
    int li = blockIdx.y;
    int tid = threadIdx.x;
    for (int j = tid; j < Gg * Ff; j += 256) sW1[j] = mw1[li * Gg * Ff + j];
    for (int j = tid; j < Ff * Ff; j += 256) sW2[j] = mw2[li * Ff * Ff + j];
    int sub = tid >> 6, f = tid & 63;
    float b1 = __ldg(mb1 + li * Ff + f);
    float b2 = __ldg(mb2 + li * Ff + f);
    __syncthreads();
    for (int c = 0; c < 16; c++) {
        int bin = blockIdx.x * 64 + c * 4 + sub;
        float d = bin * HSTEP;
        if (f < Gg) { float dd = d - f * STEP_; sg[sub][f] = __expf(COEFF_ * dd * dd); }
        __syncthreads();
        float a = b1;
        #pragma unroll
        for (int g = 0; g < Gg; g++) a += sg[sub][g] * sW1[g * Ff + f];
        sa[sub][f] = sspf(a);
        __syncthreads();
        float w = b2;
        #pragma unroll 8
        for (int k = 0; k < Ff; k++) w += sa[sub][k] * sW2[k * Ff + f];
        g_tab[((size_t)li * BINS + bin) * Ff + f] = w;
        __syncthreads();
    }
}

// ---------------- generic node GEMM (128x64 tile, 8x4 microtile, XOR-swizzled A) ----
// MODE 0: g_t1 = g_h @ W            (K=128, NC=64,  no bias, no act)
// MODE 1: g_x  = ssp(g_agg @ W + b) (K=64,  NC=128)
// MODE 2: g_h += g_x @ W + b        (K=128, NC=128)
// MODE 3: g_t1 = ssp(g_h @ W + b)   (K=128, NC=64)   [output MLP layer 1]
template <int MODE>
__global__ __launch_bounds__(256) void gemm_node(const float* __restrict__ W,
                                                 const float* __restrict__ bias)
{
    constexpr int K  = (MODE == 1) ? 64 : 128;
    constexpr int NC = (MODE == 0 || MODE == 3) ? 64 : 128;
    const float* __restrict__ A = (MODE == 0 || MODE == 3) ? g_h : (MODE == 1) ? g_agg : g_x;
    float* __restrict__ out = (MODE == 0 || MODE == 3) ? g_t1 : (MODE == 1) ? g_x : g_h;

    __shared__ float s_a[128 * 64];
    __shared__ float s_b[64 * 64];
    int tid = threadIdx.x;
    int tx = tid & 15, ty = tid >> 4;
    int rowBase = blockIdx.x * 128;
    int colBase = blockIdx.y * 64;
    float acc[8][4];
    #pragma unroll
    for (int r = 0; r < 8; r++)
        #pragma unroll
        for (int c = 0; c < 4; c++) acc[r][c] = 0.0f;

    for (int kc = 0; kc < K; kc += 64) {
        #pragma unroll
        for (int p = 0; p < 8; p++) {
            int row = p * 16 + ty;
            int rg = rowBase + row;
            float4 v = make_float4(0.f, 0.f, 0.f, 0.f);
            if (rg < Nn) v = *(const float4*)&A[(size_t)rg * K + kc + tx * 4];
            *(float4*)&s_a[row * 64 + ((tx ^ (row & 15)) << 2)] = v;
        }
        #pragma unroll
        for (int p = 0; p < 4; p++) {
            int kr = p * 16 + ty;
            *(float4*)&s_b[kr * 64 + tx * 4] =
                *(const float4*)&W[(size_t)(kc + kr) * NC + colBase + tx * 4];
        }
        __syncthreads();
        #pragma unroll 4
        for (int k4 = 0; k4 < 16; k4++) {
            float4 b0 = *(const float4*)&s_b[(k4 * 4 + 0) * 64 + tx * 4];
            float4 b1 = *(const float4*)&s_b[(k4 * 4 + 1) * 64 + tx * 4];
            float4 b2 = *(const float4*)&s_b[(k4 * 4 + 2) * 64 + tx * 4];
            float4 b3 = *(const float4*)&s_b[(k4 * 4 + 3) * 64 + tx * 4];
            #pragma unroll
            for (int r = 0; r < 8; r++) {
                int row = ty * 8 + r;
                float4 a = *(const float4*)&s_a[row * 64 + ((k4 ^ (row & 15)) << 2)];
                acc[r][0] += a.x * b0.x; acc[r][0] += a.y * b1.x;
                acc[r][0] += a.z * b2.x; acc[r][0] += a.w * b3.x;
                acc[r][1] += a.x * b0.y; acc[r][1] += a.y * b1.y;
                acc[r][1] += a.z * b2.y; acc[r][1] += a.w * b3.y;
                acc[r][2] += a.x * b0.z; acc[r][2] += a.y * b1.z;
                acc[r][2] += a.z * b2.z; acc[r][2] += a.w * b3.z;
                acc[r][3] += a.x * b0.w; acc[r][3] += a.y * b1.w;
                acc[r][3] += a.z * b2.w; acc[r][3] += a.w * b3.w;
            }
        }
        __syncthreads();
    }
    #pragma unroll
    for (int r = 0; r < 8; r++) {
        int rg = rowBase + ty * 8 + r;
        if (rg >= Nn) continue;
        int cg = colBase + tx * 4;
        float4 o = make_float4(acc[r][0], acc[r][1], acc[r][2], acc[r][3]);
        if (MODE != 0) {
            o.x += __ldg(bias + cg + 0); o.y += __ldg(bias + cg + 1);
            o.z += __ldg(bias + cg + 2); o.w += __ldg(bias + cg + 3);
        }
        if (MODE == 1 || MODE == 3) {
            o.x = sspf(o.x); o.y = sspf(o.y); o.z = sspf(o.z); o.w = sspf(o.w);
        }
        float* dst = &out[(size_t)rg * NC + cg];
        if (MODE == 2) {
            float4 cur = *(float4*)dst;
            o.x += cur.x; o.y += cur.y; o.z += cur.z; o.w += cur.w;
        }
        *(float4*)dst = o;
    }
}

// ---------------- edge aggregation: warp per node, gather over CSR, no atomics ----
__global__ __launch_bounds__(256) void edge_agg(int layer) {
    int warp = (blockIdx.x * 256 + threadIdx.x) >> 5;   // node id
    if (warp >= Nn) return;
    int lane = threadIdx.x & 31;
    int beg = __ldg(&g_rowptr[warp]);
    int end = __ldg(&g_rowptr[warp + 1]);
    const float* __restrict__ tabL = g_tab + (size_t)layer * BINS * Ff;
    float2 acc = make_float2(0.f, 0.f);
    int k = beg;
    for (; k + 1 < end; k += 2) {
        int4 e0 = __ldg(&g_cs[k]);
        int4 e1 = __ldg(&g_cs[k + 1]);
        float2 x0 = *(const float2*)(g_t1 + (size_t)e0.x * Ff + lane * 2);
        float2 x1 = *(const float2*)(g_t1 + (size_t)e1.x * Ff + lane * 2);
        float2 a0 = *(const float2*)(tabL + (size_t)e0.y * Ff + lane * 2);
        float2 b0 = *(const float2*)(tabL + (size_t)(e0.y + 1) * Ff + lane * 2);
        float2 a1 = *(const float2*)(tabL + (size_t)e1.y * Ff + lane * 2);
        float2 b1 = *(const float2*)(tabL + (size_t)(e1.y + 1) * Ff + lane * 2);
        float u0 = __int_as_float(e0.z), v0 = __int_as_float(e0.w);
        float u1 = __int_as_float(e1.z), v1 = __int_as_float(e1.w);
        acc.x += (u0 * a0.x + v0 * b0.x) * x0.x;
        acc.y += (u0 * a0.y + v0 * b0.y) * x0.y;
        acc.x += (u1 * a1.x + v1 * b1.x) * x1.x;
        acc.y += (u1 * a1.y + v1 * b1.y) * x1.y;
    }
    if (k < end) {
        int4 e0 = __ldg(&g_cs[k]);
        float2 x0 = *(const float2*)(g_t1 + (size_t)e0.x * Ff + lane * 2);
        float2 a0 = *(const float2*)(tabL + (size_t)e0.y * Ff + lane * 2);
        float2 b0 = *(const float2*)(tabL + (size_t)(e0.y + 1) * Ff + lane * 2);
        float u0 = __int_as_float(e0.z), v0 = __int_as_float(e0.w);
        acc.x += (u0 * a0.x + v0 * b0.x) * x0.x;
        acc.y += (u0 * a0.y + v0 * b0.y) * x0.y;
    }
    *(float2*)(g_agg + (size_t)warp * Ff + lane * 2) = acc;
}

// ---------------- zero out ----------------
__global__ void zero_out(float* out) {
    if (threadIdx.x < NGg) out[threadIdx.x] = 0.0f;
}

// ---------------- readout: y[n] = hv . ow2 + ob2, scatter into graphs ----------------
__global__ void reduce_out(const int* __restrict__ batch, const float* __restrict__ ow2,
                           const float* __restrict__ ob2, float* __restrict__ out)
{
    int n = blockIdx.x * 256 + threadIdx.x;
    if (n >= Nn) return;
    const float4* hv = (const float4*)(g_t1 + (size_t)n * Ff);
    float s = 0.0f;
    #pragma unroll
    for (int j = 0; j < 16; j++) {
        float4 a = __ldg(hv + j);
        float4 w = __ldg((const float4*)ow2 + j);
        s += a.x * w.x + a.y * w.y + a.z * w.z + a.w * w.w;
    }
    atomicAdd(&out[__ldg(batch + n)], s + __ldg(ob2));
}

// ---------------- host ----------------
extern "C" void kernel_launch(void* const* d_in, const int* in_sizes, int n_in,
                              void* d_out, int out_size)
{
    const int*   z    = (const int*)  d_in[0];
    const float* pos  = (const float*)d_in[1];
    const int*   batch= (const int*)  d_in[2];
    const int*   ei   = (const int*)  d_in[3];
    const float* emb  = (const float*)d_in[4];
    const float* mw1  = (const float*)d_in[5];
    const float* mb1  = (const float*)d_in[6];
    const float* mw2  = (const float*)d_in[7];
    const float* mb2  = (const float*)d_in[8];
    const float* l1w  = (const float*)d_in[9];
    const float* l2w  = (const float*)d_in[10];
    const float* l2b  = (const float*)d_in[11];
    const float* lw   = (const float*)d_in[12];
    const float* lb   = (const float*)d_in[13];
    const float* ow1  = (const float*)d_in[14];
    const float* ob1  = (const float*)d_in[15];
    const float* ow2  = (const float*)d_in[16];
    const float* ob2  = (const float*)d_in[17];
    float* out = (float*)d_out;

    init_h<<<Nn * Hh / 4 / 256, 256>>>(z, emb);
    zero_cnt<<<(Nn + 255) / 256, 256>>>();
    count_dst<<<(Ee + 255) / 256, 256>>>(ei);
    scan_counts<<<1, 1024>>>();
    edge_prep_fill<<<(Ee + 255) / 256, 256>>>(pos, ei);
    build_tab<<<dim3(BINS / 64, Ll), 256>>>(mw1, mb1, mw2, mb2);

    const int NB = (Nn + 127) / 128;                             // 391
    for (int i = 0; i < Ll; i++) {
        gemm_node<0><<<dim3(NB, 1), 256>>>(l1w + i * Hh * Ff, nullptr);
        edge_agg<<<(Nn * 32 + 255) / 256, 256>>>(i);
        gemm_node<1><<<dim3(NB, 2), 256>>>(l2w + i * Ff * Hh, l2b + i * Hh);
        gemm_node<2><<<dim3(NB, 2), 256>>>(lw + i * Hh * Hh, lb + i * Hh);
    }
    zero_out<<<1, 256>>>(out);
    gemm_node<3><<<dim3(NB, 1), 256>>>(ow1, ob1);
    reduce_out<<<(Nn + 255) / 256, 256>>>(batch, ow2, ob2, out);
}

// round 4
// speedup vs baseline: 2.8281x; 1.1282x over previous
#include <cuda_runtime.h>

#define Nn 50000
#define Ee 1600000
#define Hh 128
#define Ff 64
#define Gg 50
#define Ll 3
#define NGg 256
#define BINS 16384
#define NBLK 196            // ceil(Nn/256)

#define CUTOFF 10.0f
#define STEP_  (CUTOFF / (Gg - 1))
#define COEFF_ (-0.5f / (STEP_ * STEP_))
#define TABMAX 8.6700f
#define HSTEP  (TABMAX / (BINS - 1))
#define INVH   ((BINS - 1) / TABMAX)
#define LN2    0.69314718055994531f
#define PI_F   3.14159265358979f

// ---------------- scratch ----------------
__device__ __align__(16) float g_h[Nn * Hh];
__device__ __align__(16) float g_t1[Nn * Ff];
__device__ __align__(16) float g_agg[Nn * Ff];
__device__ __align__(16) float g_x[Nn * Hh];
__device__ __align__(16) float g_tab[(size_t)Ll * BINS * Ff];
__device__ __align__(16) int4 g_cs[Ee];
__device__ int g_cnt[Nn];
__device__ int g_rowptr[Nn + 1];
__device__ int g_cur[Nn];
__device__ int g_bsum[256];
__device__ int g_boff[256];

__device__ __forceinline__ float sspf(float x) {
    float sp = (x > 20.0f) ? x : log1pf(__expf(x));
    return sp - LN2;
}
__device__ __forceinline__ unsigned f2tf32(float x) {
    unsigned u;
    asm("cvt.rna.tf32.f32 %0, %1;" : "=r"(u) : "f"(x));
    return u;
}
__device__ __forceinline__ void mma8(float* c, const unsigned* a, unsigned b0, unsigned b1) {
    asm volatile(
        "mma.sync.aligned.m16n8k8.row.col.f32.tf32.tf32.f32 "
        "{%0,%1,%2,%3}, {%4,%5,%6,%7}, {%8,%9}, {%0,%1,%2,%3};"
        : "+f"(c[0]), "+f"(c[1]), "+f"(c[2]), "+f"(c[3])
        : "r"(a[0]), "r"(a[1]), "r"(a[2]), "r"(a[3]), "r"(b0), "r"(b1));
}

// ---------------- h init ----------------
__global__ void init_h(const int* __restrict__ z, const float* __restrict__ emb) {
    int i = blockIdx.x * 256 + threadIdx.x;
    int n = i >> 5, c = i & 31;
    ((float4*)g_h)[i] = ((const float4*)emb)[(size_t)__ldg(z + n) * 32 + c];
}

// ---------------- CSR build ----------------
__global__ void zero_cnt() {
    int i = blockIdx.x * 256 + threadIdx.x;
    if (i < Nn) g_cnt[i] = 0;
}
__global__ void count_dst(const int* __restrict__ ei) {
    int e = blockIdx.x * 256 + threadIdx.x;
    if (e < Ee) atomicAdd(&g_cnt[__ldg(ei + Ee + e)], 1);
}
__global__ void scan_a() {
    __shared__ int s[256];
    int i = blockIdx.x * 256 + threadIdx.x;
    int v = (i < Nn) ? g_cnt[i] : 0;
    s[threadIdx.x] = v;
    __syncthreads();
    for (int o = 128; o > 0; o >>= 1) {
        if (threadIdx.x < o) s[threadIdx.x] += s[threadIdx.x + o];
        __syncthreads();
    }
    if (threadIdx.x == 0) g_bsum[blockIdx.x] = s[0];
}
__global__ void scan_b() {
    __shared__ int s[256];
    int t = threadIdx.x;
    s[t] = (t < NBLK) ? g_bsum[t] : 0;
    __syncthreads();
    for (int o = 1; o < 256; o <<= 1) {
        int v = (t >= o) ? s[t - o] : 0;
        __syncthreads();
        s[t] += v;
        __syncthreads();
    }
    g_boff[t] = (t == 0) ? 0 : s[t - 1];
}
__global__ void scan_c() {
    __shared__ int s[256];
    int t = threadIdx.x;
    int i = blockIdx.x * 256 + t;
    int v = (i < Nn) ? g_cnt[i] : 0;
    s[t] = v;
    __syncthreads();
    for (int o = 1; o < 256; o <<= 1) {
        int x = (t >= o) ? s[t - o] : 0;
        __syncthreads();
        s[t] += x;
        __syncthreads();
    }
    int excl = s[t] - v + g_boff[blockIdx.x];
    if (i < Nn) {
        g_rowptr[i] = excl;
        g_cur[i] = excl;
        if (i == Nn - 1) g_rowptr[Nn] = excl + v;
    }
}

// ---------------- fused edge prep + CSR fill ----------------
__global__ void edge_prep_fill(const float* __restrict__ pos, const int* __restrict__ ei) {
    int e = blockIdx.x * 256 + threadIdx.x;
    if (e >= Ee) return;
    int s = __ldg(ei + e);
    int t = __ldg(ei + Ee + e);
    float dx = __ldg(pos + s * 3 + 0) - __ldg(pos + t * 3 + 0);
    float dy = __ldg(pos + s * 3 + 1) - __ldg(pos + t * 3 + 1);
    float dz = __ldg(pos + s * 3 + 2) - __ldg(pos + t * 3 + 2);
    float d = sqrtf(dx * dx + dy * dy + dz * dz);
    float C = 0.5f * (cosf(d * (PI_F / CUTOFF)) + 1.0f);
    float tt = d * INVH;
    int b = (int)tt;
    if (b > BINS - 2) b = BINS - 2;
    float fr = tt - (float)b;
    float u = C * (1.0f - fr);
    float v = C * fr;
    int p = atomicAdd(&g_cur[t], 1);
    g_cs[p] = make_int4(s, b, __float_as_int(u), __float_as_int(v));
}

// ---------------- W(d) table build ----------------
__global__ __launch_bounds__(256) void build_tab(
    const float* __restrict__ mw1, const float* __restrict__ mb1,
    const float* __restrict__ mw2, const float* __restrict__ mb2)
{
    __shared__ float sW1[Gg * Ff];
    __shared__ float sW2[Ff * Ff];
    __shared__ float sg[4][Gg];
    __shared__ float sa[4][Ff];
    int li = blockIdx.y;
    int tid = threadIdx.x;
    for (int j = tid; j < Gg * Ff; j += 256) sW1[j] = mw1[li * Gg * Ff + j];
    for (int j = tid; j < Ff * Ff; j += 256) sW2[j] = mw2[li * Ff * Ff + j];
    int sub = tid >> 6, f = tid & 63;
    float b1 = __ldg(mb1 + li * Ff + f);
    float b2 = __ldg(mb2 + li * Ff + f);
    __syncthreads();
    for (int c = 0; c < 16; c++) {
        int bin = blockIdx.x * 64 + c * 4 + sub;
        float d = bin * HSTEP;
        if (f < Gg) { float dd = d - f * STEP_; sg[sub][f] = __expf(COEFF_ * dd * dd); }
        __syncthreads();
        float a = b1;
        #pragma unroll
        for (int g = 0; g < Gg; g++) a += sg[sub][g] * sW1[g * Ff + f];
        sa[sub][f] = sspf(a);
        __syncthreads();
        float w = b2;
        #pragma unroll 8
        for (int k = 0; k < Ff; k++) w += sa[sub][k] * sW2[k * Ff + f];
        g_tab[((size_t)li * BINS + bin) * Ff + f] = w;
        __syncthreads();
    }
}

// ---------------- tf32 mma.sync node GEMM ----------------
// 256-row tile per block, 8 warps, warp = 32 rows x NC cols, K chunked by 32.
// MODE 0: g_t1 = g_h @ W            (K=128, NC=64)
// MODE 1: g_x  = ssp(g_agg @ W + b) (K=64,  NC=128)
// MODE 2: g_h += g_x @ W + b        (K=128, NC=128)
// MODE 3: g_t1 = ssp(g_h @ W + b)   (K=128, NC=64)
template <int MODE>
__global__ __launch_bounds__(256) void mma_gemm(const float* __restrict__ Wt,
                                                const float* __restrict__ bias)
{
    constexpr int K  = (MODE == 1) ? 64 : 128;
    constexpr int NC = (MODE == 0 || MODE == 3) ? 64 : 128;
    constexpr int NT = NC / 8;
    constexpr int PB = NC + 8;                  // B smem stride (mod 32 == 8)
    constexpr int PA = 36;                      // A smem stride (mod 32 == 4)
    const float* __restrict__ A = (MODE == 0 || MODE == 3) ? g_h : (MODE == 1) ? g_agg : g_x;
    float* __restrict__ out = (MODE == 0 || MODE == 3) ? g_t1 : (MODE == 1) ? g_x : g_h;

    extern __shared__ float sm[];
    unsigned* As = (unsigned*)sm;               // 256 x PA tf32
    unsigned* Bs = (unsigned*)(sm + 256 * PA);  // 32 x PB tf32
    int tid = threadIdx.x;
    int w = tid >> 5, lane = tid & 31, g = lane >> 2, tg = lane & 3;
    int rowBase = blockIdx.x * 256;

    float acc[2][NT][4];
    #pragma unroll
    for (int mt = 0; mt < 2; mt++)
        #pragma unroll
        for (int nt = 0; nt < NT; nt++)
            #pragma unroll
            for (int j = 0; j < 4; j++) acc[mt][nt][j] = 0.0f;

    for (int kc = 0; kc < K; kc += 32) {
        // stage A chunk [256 x 32]
        #pragma unroll
        for (int it = 0; it < 8; it++) {
            int idx = it * 256 + tid;
            int row = idx >> 3, q = idx & 7;
            int ar = rowBase + row;
            if (ar > Nn - 1) ar = Nn - 1;
            float4 v = *(const float4*)(A + (size_t)ar * K + kc + q * 4);
            unsigned* d = As + row * PA + q * 4;
            d[0] = f2tf32(v.x); d[1] = f2tf32(v.y);
            d[2] = f2tf32(v.z); d[3] = f2tf32(v.w);
        }
        // stage B chunk [32 x NC]
        #pragma unroll
        for (int it = 0; it < NC / 32; it++) {
            int idx = it * 256 + tid;
            int k = idx / (NC / 4), n4 = idx % (NC / 4);
            float4 v = *(const float4*)(Wt + (size_t)(kc + k) * NC + n4 * 4);
            unsigned* d = Bs + k * PB + n4 * 4;
            d[0] = f2tf32(v.x); d[1] = f2tf32(v.y);
            d[2] = f2tf32(v.z); d[3] = f2tf32(v.w);
        }
        __syncthreads();
        #pragma unroll
        for (int s = 0; s < 4; s++) {
            unsigned a[2][4];
            #pragma unroll
            for (int mt = 0; mt < 2; mt++) {
                int r0 = w * 32 + mt * 16 + g;
                a[mt][0] = As[r0 * PA + s * 8 + tg];
                a[mt][1] = As[(r0 + 8) * PA + s * 8 + tg];
                a[mt][2] = As[r0 * PA + s * 8 + tg + 4];
                a[mt][3] = As[(r0 + 8) * PA + s * 8 + tg + 4];
            }
            #pragma unroll
            for (int nt = 0; nt < NT; nt++) {
                unsigned b0 = Bs[(s * 8 + tg) * PB + nt * 8 + g];
                unsigned b1 = Bs[(s * 8 + tg + 4) * PB + nt * 8 + g];
                mma8(acc[0][nt], a[0], b0, b1);
                mma8(acc[1][nt], a[1], b0, b1);
            }
        }
        __syncthreads();
    }
    // epilogue
    #pragma unroll
    for (int mt = 0; mt < 2; mt++) {
        int r0 = rowBase + w * 32 + mt * 16 + g;
        #pragma unroll
        for (int nt = 0; nt < NT; nt++) {
            int col = nt * 8 + tg * 2;
            float2 bv = make_float2(0.f, 0.f);
            if (MODE != 0) bv = *(const float2*)(bias + col);
            #pragma unroll
            for (int half = 0; half < 2; half++) {
                int r = r0 + half * 8;
                if (r >= Nn) continue;
                float2 o = make_float2(acc[mt][nt][half * 2] + bv.x,
                                       acc[mt][nt][half * 2 + 1] + bv.y);
                if (MODE == 1 || MODE == 3) { o.x = sspf(o.x); o.y = sspf(o.y); }
                float* dst = out + (size_t)r * NC + col;
                if (MODE == 2) {
                    float2 cur = *(float2*)dst;
                    o.x += cur.x; o.y += cur.y;
                }
                *(float2*)dst = o;
            }
        }
    }
}

// ---------------- edge aggregation: warp per node, CSR gather, no atomics ----
__global__ __launch_bounds__(256) void edge_agg(int layer) {
    int warp = (blockIdx.x * 256 + threadIdx.x) >> 5;
    if (warp >= Nn) return;
    int lane = threadIdx.x & 31;
    int beg = __ldg(&g_rowptr[warp]);
    int end = __ldg(&g_rowptr[warp + 1]);
    const float* __restrict__ tabL = g_tab + (size_t)layer * BINS * Ff;
    float2 acc = make_float2(0.f, 0.f);
    int k = beg;
    for (; k + 1 < end; k += 2) {
        int4 e0 = __ldg(&g_cs[k]);
        int4 e1 = __ldg(&g_cs[k + 1]);
        float2 x0 = *(const float2*)(g_t1 + (size_t)e0.x * Ff + lane * 2);
        float2 x1 = *(const float2*)(g_t1 + (size_t)e1.x * Ff + lane * 2);
        float2 a0 = *(const float2*)(tabL + (size_t)e0.y * Ff + lane * 2);
        float2 b0 = *(const float2*)(tabL + (size_t)(e0.y + 1) * Ff + lane * 2);
        float2 a1 = *(const float2*)(tabL + (size_t)e1.y * Ff + lane * 2);
        float2 b1 = *(const float2*)(tabL + (size_t)(e1.y + 1) * Ff + lane * 2);
        float u0 = __int_as_float(e0.z), v0 = __int_as_float(e0.w);
        float u1 = __int_as_float(e1.z), v1 = __int_as_float(e1.w);
        acc.x += (u0 * a0.x + v0 * b0.x) * x0.x;
        acc.y += (u0 * a0.y + v0 * b0.y) * x0.y;
        acc.x += (u1 * a1.x + v1 * b1.x) * x1.x;
        acc.y += (u1 * a1.y + v1 * b1.y) * x1.y;
    }
    if (k < end) {
        int4 e0 = __ldg(&g_cs[k]);
        float2 x0 = *(const float2*)(g_t1 + (size_t)e0.x * Ff + lane * 2);
        float2 a0 = *(const float2*)(tabL + (size_t)e0.y * Ff + lane * 2);
        float2 b0 = *(const float2*)(tabL + (size_t)(e0.y + 1) * Ff + lane * 2);
        float u0 = __int_as_float(e0.z), v0 = __int_as_float(e0.w);
        acc.x += (u0 * a0.x + v0 * b0.x) * x0.x;
        acc.y += (u0 * a0.y + v0 * b0.y) * x0.y;
    }
    *(float2*)(g_agg + (size_t)warp * Ff + lane * 2) = acc;
}

// ---------------- output ----------------
__global__ void zero_out(float* out) {
    if (threadIdx.x < NGg) out[threadIdx.x] = 0.0f;
}
__global__ void reduce_out(const int* __restrict__ batch, const float* __restrict__ ow2,
                           const float* __restrict__ ob2, float* __restrict__ out)
{
    int n = blockIdx.x * 256 + threadIdx.x;
    if (n >= Nn) return;
    const float4* hv = (const float4*)(g_t1 + (size_t)n * Ff);
    float s = 0.0f;
    #pragma unroll
    for (int j = 0; j < 16; j++) {
        float4 a = __ldg(hv + j);
        float4 w = __ldg((const float4*)ow2 + j);
        s += a.x * w.x + a.y * w.y + a.z * w.z + a.w * w.w;
    }
    atomicAdd(&out[__ldg(batch + n)], s + __ldg(ob2));
}

// ---------------- host ----------------
extern "C" void kernel_launch(void* const* d_in, const int* in_sizes, int n_in,
                              void* d_out, int out_size)
{
    const int*   z    = (const int*)  d_in[0];
    const float* pos  = (const float*)d_in[1];
    const int*   batch= (const int*)  d_in[2];
    const int*   ei   = (const int*)  d_in[3];
    const float* emb  = (const float*)d_in[4];
    const float* mw1  = (const float*)d_in[5];
    const float* mb1  = (const float*)d_in[6];
    const float* mw2  = (const float*)d_in[7];
    const float* mb2  = (const float*)d_in[8];
    const float* l1w  = (const float*)d_in[9];
    const float* l2w  = (const float*)d_in[10];
    const float* l2b  = (const float*)d_in[11];
    const float* lw   = (const float*)d_in[12];
    const float* lb   = (const float*)d_in[13];
    const float* ow1  = (const float*)d_in[14];
    const float* ob1  = (const float*)d_in[15];
    const float* ow2  = (const float*)d_in[16];
    const float* ob2  = (const float*)d_in[17];
    float* out = (float*)d_out;

    const int SMA = 256 * 36 * 4;                 // A stage bytes
    const int SM64  = SMA + 32 * (64 + 8) * 4;    // 46080 (modes 0,3)
    const int SM128 = SMA + 32 * (128 + 8) * 4;   // 54272 (modes 1,2)
    cudaFuncSetAttribute(mma_gemm<0>, cudaFuncAttributeMaxDynamicSharedMemorySize, SM64);
    cudaFuncSetAttribute(mma_gemm<1>, cudaFuncAttributeMaxDynamicSharedMemorySize, SM128);
    cudaFuncSetAttribute(mma_gemm<2>, cudaFuncAttributeMaxDynamicSharedMemorySize, SM128);
    cudaFuncSetAttribute(mma_gemm<3>, cudaFuncAttributeMaxDynamicSharedMemorySize, SM64);

    init_h<<<Nn * Hh / 4 / 256, 256>>>(z, emb);
    zero_cnt<<<(Nn + 255) / 256, 256>>>();
    count_dst<<<(Ee + 255) / 256, 256>>>(ei);
    scan_a<<<NBLK, 256>>>();
    scan_b<<<1, 256>>>();
    scan_c<<<NBLK, 256>>>();
    edge_prep_fill<<<(Ee + 255) / 256, 256>>>(pos, ei);
    build_tab<<<dim3(BINS / 64, Ll), 256>>>(mw1, mb1, mw2, mb2);

    const int NBG = (Nn + 255) / 256;             // 196
    for (int i = 0; i < Ll; i++) {
        mma_gemm<0><<<NBG, 256, SM64>>>(l1w + i * Hh * Ff, nullptr);
        edge_agg<<<(Nn * 32 + 255) / 256, 256>>>(i);
        mma_gemm<1><<<NBG, 256, SM128>>>(l2w + i * Ff * Hh, l2b + i * Hh);
        mma_gemm<2><<<NBG, 256, SM128>>>(lw + i * Hh * Hh, lb + i * Hh);
    }
    zero_out<<<1, 256>>>(out);
    mma_gemm<3><<<NBG, 256, SM64>>>(ow1, ob1);
    reduce_out<<<(Nn + 255) / 256, 256>>>(batch, ow2, ob2, out);
}

// round 5
// speedup vs baseline: 3.1768x; 1.1233x over previous
#include <cuda_runtime.h>
#include <cuda_bf16.h>

#define Nn 50000
#define Ee 1600000
#define Hh 128
#define Ff 64
#define Gg 50
#define Ll 3
#define NGg 256
#define BINS 16384
#define NBLK 196            // ceil(Nn/256)

#define CUTOFF 10.0f
#define STEP_  (CUTOFF / (Gg - 1))
#define COEFF_ (-0.5f / (STEP_ * STEP_))
#define TABMAX 8.6700f
#define HSTEP  (TABMAX / (BINS - 1))
#define INVH   ((BINS - 1) / TABMAX)
#define LN2    0.69314718055994531f
#define PI_F   3.14159265358979f

// ---------------- scratch ----------------
__device__ __align__(16) float g_h[Nn * Hh];
__device__ __align__(16) float g_t1[Nn * Ff];          // fp32 (output-MLP hidden)
__device__ __align__(16) unsigned g_xb[Nn * 32];       // bf16x2 t1 for edge_agg
__device__ __align__(16) float g_agg[Nn * Ff];
__device__ __align__(16) float g_x[Nn * Hh];
__device__ __align__(16) unsigned short g_tabh[(size_t)Ll * BINS * Ff];  // bf16 W*C table
__device__ __align__(16) int2 g_cse[Ee];               // CSR edges: {src, bin<<16|fr16}
__device__ int g_cnt[Nn];
__device__ int g_rowptr[Nn + 1];
__device__ int g_cur[Nn];
__device__ int g_bsum[256];
__device__ int g_boff[256];

__device__ __forceinline__ float sspf(float x) {
    float sp = (x > 20.0f) ? x : log1pf(__expf(x));
    return sp - LN2;
}
__device__ __forceinline__ unsigned f2tf32(float x) {
    unsigned u;
    asm("cvt.rna.tf32.f32 %0, %1;" : "=r"(u) : "f"(x));
    return u;
}
__device__ __forceinline__ unsigned pack_bf16x2(float lo, float hi) {
    unsigned r;
    asm("cvt.rn.bf16x2.f32 %0, %1, %2;" : "=r"(r) : "f"(hi), "f"(lo));
    return r;
}
__device__ __forceinline__ float2 unpack_bf16x2(unsigned p) {
    float2 r;
    r.x = __uint_as_float(p << 16);
    r.y = __uint_as_float(p & 0xFFFF0000u);
    return r;
}
__device__ __forceinline__ void mma8(float* c, const unsigned* a, unsigned b0, unsigned b1) {
    asm volatile(
        "mma.sync.aligned.m16n8k8.row.col.f32.tf32.tf32.f32 "
        "{%0,%1,%2,%3}, {%4,%5,%6,%7}, {%8,%9}, {%0,%1,%2,%3};"
        : "+f"(c[0]), "+f"(c[1]), "+f"(c[2]), "+f"(c[3])
        : "r"(a[0]), "r"(a[1]), "r"(a[2]), "r"(a[3]), "r"(b0), "r"(b1));
}

// ---------------- h init ----------------
__global__ void init_h(const int* __restrict__ z, const float* __restrict__ emb) {
    int i = blockIdx.x * 256 + threadIdx.x;
    int n = i >> 5, c = i & 31;
    ((float4*)g_h)[i] = ((const float4*)emb)[(size_t)__ldg(z + n) * 32 + c];
}

// ---------------- CSR build ----------------
__global__ void zero_cnt() {
    int i = blockIdx.x * 256 + threadIdx.x;
    if (i < Nn) g_cnt[i] = 0;
}
__global__ void count_dst(const int* __restrict__ ei) {
    int e = blockIdx.x * 256 + threadIdx.x;
    if (e < Ee) atomicAdd(&g_cnt[__ldg(ei + Ee + e)], 1);
}
__global__ void scan_a() {
    __shared__ int s[256];
    int i = blockIdx.x * 256 + threadIdx.x;
    int v = (i < Nn) ? g_cnt[i] : 0;
    s[threadIdx.x] = v;
    __syncthreads();
    for (int o = 128; o > 0; o >>= 1) {
        if (threadIdx.x < o) s[threadIdx.x] += s[threadIdx.x + o];
        __syncthreads();
    }
    if (threadIdx.x == 0) g_bsum[blockIdx.x] = s[0];
}
__global__ void scan_b() {
    __shared__ int s[256];
    int t = threadIdx.x;
    s[t] = (t < NBLK) ? g_bsum[t] : 0;
    __syncthreads();
    for (int o = 1; o < 256; o <<= 1) {
        int v = (t >= o) ? s[t - o] : 0;
        __syncthreads();
        s[t] += v;
        __syncthreads();
    }
    g_boff[t] = (t == 0) ? 0 : s[t - 1];
}
__global__ void scan_c() {
    __shared__ int s[256];
    int t = threadIdx.x;
    int i = blockIdx.x * 256 + t;
    int v = (i < Nn) ? g_cnt[i] : 0;
    s[t] = v;
    __syncthreads();
    for (int o = 1; o < 256; o <<= 1) {
        int x = (t >= o) ? s[t - o] : 0;
        __syncthreads();
        s[t] += x;
        __syncthreads();
    }
    int excl = s[t] - v + g_boff[blockIdx.x];
    if (i < Nn) {
        g_rowptr[i] = excl;
        g_cur[i] = excl;
        if (i == Nn - 1) g_rowptr[Nn] = excl + v;
    }
}

// ---------------- fused edge prep + CSR fill (8-byte records) ----------------
__global__ void edge_prep_fill(const float* __restrict__ pos, const int* __restrict__ ei) {
    int e = blockIdx.x * 256 + threadIdx.x;
    if (e >= Ee) return;
    int s = __ldg(ei + e);
    int t = __ldg(ei + Ee + e);
    float dx = __ldg(pos + s * 3 + 0) - __ldg(pos + t * 3 + 0);
    float dy = __ldg(pos + s * 3 + 1) - __ldg(pos + t * 3 + 1);
    float dz = __ldg(pos + s * 3 + 2) - __ldg(pos + t * 3 + 2);
    float d = sqrtf(dx * dx + dy * dy + dz * dz);
    float tt = d * INVH;
    int b = (int)tt;
    if (b > BINS - 2) b = BINS - 2;
    float fr = tt - (float)b;
    int fr16 = (int)(fr * 65535.0f + 0.5f);
    if (fr16 > 65535) fr16 = 65535;
    int p = atomicAdd(&g_cur[t], 1);
    g_cse[p] = make_int2(s, (b << 16) | fr16);
}

// ---------------- W(d)*C(d) table build (bf16) ----------------
__global__ __launch_bounds__(256) void build_tab(
    const float* __restrict__ mw1, const float* __restrict__ mb1,
    const float* __restrict__ mw2, const float* __restrict__ mb2)
{
    __shared__ float sW1[Gg * Ff];
    __shared__ float sW2[Ff * Ff];
    __shared__ float sg[4][Gg];
    __shared__ float sa[4][Ff];
    int li = blockIdx.y;
    int tid = threadIdx.x;
    for (int j = tid; j < Gg * Ff; j += 256) sW1[j] = mw1[li * Gg * Ff + j];
    for (int j = tid; j < Ff * Ff; j += 256) sW2[j] = mw2[li * Ff * Ff + j];
    int sub = tid >> 6, f = tid & 63;
    float b1 = __ldg(mb1 + li * Ff + f);
    float b2 = __ldg(mb2 + li * Ff + f);
    __syncthreads();
    for (int c = 0; c < 16; c++) {
        int bin = blockIdx.x * 64 + c * 4 + sub;
        float d = bin * HSTEP;
        if (f < Gg) { float dd = d - f * STEP_; sg[sub][f] = __expf(COEFF_ * dd * dd); }
        __syncthreads();
        float a = b1;
        #pragma unroll
        for (int g = 0; g < Gg; g++) a += sg[sub][g] * sW1[g * Ff + f];
        sa[sub][f] = sspf(a);
        __syncthreads();
        float w = b2;
        #pragma unroll 8
        for (int k = 0; k < Ff; k++) w += sa[sub][k] * sW2[k * Ff + f];
        float C = 0.5f * (cosf(d * (PI_F / CUTOFF)) + 1.0f);
        g_tabh[((size_t)li * BINS + bin) * Ff + f] = __bfloat16_as_ushort(__float2bfloat16(w * C));
        __syncthreads();
    }
}

// ---------------- tf32 mma.sync node GEMM ----------------
// MODE 0: g_xb = bf16(g_h @ W)      (K=128, NC=64)
// MODE 1: g_x  = ssp(g_agg @ W + b) (K=64,  NC=128)
// MODE 2: g_h += g_x @ W + b        (K=128, NC=128)
// MODE 3: g_t1 = ssp(g_h @ W + b)   (K=128, NC=64)
template <int MODE>
__global__ __launch_bounds__(256) void mma_gemm(const float* __restrict__ Wt,
                                                const float* __restrict__ bias)
{
    constexpr int K  = (MODE == 1) ? 64 : 128;
    constexpr int NC = (MODE == 0 || MODE == 3) ? 64 : 128;
    constexpr int NT = NC / 8;
    constexpr int PB = NC + 8;
    constexpr int PA = 36;
    const float* __restrict__ A = (MODE == 0 || MODE == 3) ? g_h : (MODE == 1) ? g_agg : g_x;
    float* __restrict__ out = (MODE == 3) ? g_t1 : (MODE == 1) ? g_x : g_h;

    extern __shared__ float sm[];
    unsigned* As = (unsigned*)sm;
    unsigned* Bs = (unsigned*)(sm + 256 * PA);
    int tid = threadIdx.x;
    int w = tid >> 5, lane = tid & 31, g = lane >> 2, tg = lane & 3;
    int rowBase = blockIdx.x * 256;

    float acc[2][NT][4];
    #pragma unroll
    for (int mt = 0; mt < 2; mt++)
        #pragma unroll
        for (int nt = 0; nt < NT; nt++)
            #pragma unroll
            for (int j = 0; j < 4; j++) acc[mt][nt][j] = 0.0f;

    for (int kc = 0; kc < K; kc += 32) {
        #pragma unroll
        for (int it = 0; it < 8; it++) {
            int idx = it * 256 + tid;
            int row = idx >> 3, q = idx & 7;
            int ar = rowBase + row;
            if (ar > Nn - 1) ar = Nn - 1;
            float4 v = *(const float4*)(A + (size_t)ar * K + kc + q * 4);
            unsigned* d = As + row * PA + q * 4;
            d[0] = f2tf32(v.x); d[1] = f2tf32(v.y);
            d[2] = f2tf32(v.z); d[3] = f2tf32(v.w);
        }
        #pragma unroll
        for (int it = 0; it < NC / 32; it++) {
            int idx = it * 256 + tid;
            int k = idx / (NC / 4), n4 = idx % (NC / 4);
            float4 v = *(const float4*)(Wt + (size_t)(kc + k) * NC + n4 * 4);
            unsigned* d = Bs + k * PB + n4 * 4;
            d[0] = f2tf32(v.x); d[1] = f2tf32(v.y);
            d[2] = f2tf32(v.z); d[3] = f2tf32(v.w);
        }
        __syncthreads();
        #pragma unroll
        for (int s = 0; s < 4; s++) {
            unsigned a[2][4];
            #pragma unroll
            for (int mt = 0; mt < 2; mt++) {
                int r0 = w * 32 + mt * 16 + g;
                a[mt][0] = As[r0 * PA + s * 8 + tg];
                a[mt][1] = As[(r0 + 8) * PA + s * 8 + tg];
                a[mt][2] = As[r0 * PA + s * 8 + tg + 4];
                a[mt][3] = As[(r0 + 8) * PA + s * 8 + tg + 4];
            }
            #pragma unroll
            for (int nt = 0; nt < NT; nt++) {
                unsigned b0 = Bs[(s * 8 + tg) * PB + nt * 8 + g];
                unsigned b1 = Bs[(s * 8 + tg + 4) * PB + nt * 8 + g];
                mma8(acc[0][nt], a[0], b0, b1);
                mma8(acc[1][nt], a[1], b0, b1);
            }
        }
        __syncthreads();
    }
    #pragma unroll
    for (int mt = 0; mt < 2; mt++) {
        int r0 = rowBase + w * 32 + mt * 16 + g;
        #pragma unroll
        for (int nt = 0; nt < NT; nt++) {
            int col = nt * 8 + tg * 2;
            float2 bv = make_float2(0.f, 0.f);
            if (MODE != 0) bv = *(const float2*)(bias + col);
            #pragma unroll
            for (int half = 0; half < 2; half++) {
                int r = r0 + half * 8;
                if (r >= Nn) continue;
                float2 o = make_float2(acc[mt][nt][half * 2] + bv.x,
                                       acc[mt][nt][half * 2 + 1] + bv.y);
                if (MODE == 1 || MODE == 3) { o.x = sspf(o.x); o.y = sspf(o.y); }
                if (MODE == 0) {
                    g_xb[(size_t)r * 32 + (col >> 1)] = pack_bf16x2(o.x, o.y);
                } else {
                    float* dst = out + (size_t)r * NC + col;
                    if (MODE == 2) {
                        float2 cur = *(float2*)dst;
                        o.x += cur.x; o.y += cur.y;
                    }
                    *(float2*)dst = o;
                }
            }
        }
    }
}

// ---------------- edge aggregation: warp/node, bf16 table + bf16 x, no atomics ----
__global__ __launch_bounds__(256) void edge_agg(int layer) {
    int node = (blockIdx.x * 256 + threadIdx.x) >> 5;
    if (node >= Nn) return;
    int lane = threadIdx.x & 31;
    int beg = __ldg(&g_rowptr[node]);
    int end = __ldg(&g_rowptr[node + 1]);
    const unsigned* __restrict__ tabL =
        (const unsigned*)(g_tabh + (size_t)layer * BINS * Ff);
    float2 acc = make_float2(0.f, 0.f);
    int k = beg;
    for (; k + 1 < end; k += 2) {
        int2 e0 = __ldg(&g_cse[k]);
        int2 e1 = __ldg(&g_cse[k + 1]);
        int b0 = e0.y >> 16, b1 = e1.y >> 16;
        float f0 = (float)(e0.y & 0xFFFF) * (1.0f / 65535.0f);
        float f1 = (float)(e1.y & 0xFFFF) * (1.0f / 65535.0f);
        unsigned ta0 = __ldg(tabL + b0 * 32 + lane);
        unsigned tb0 = __ldg(tabL + b0 * 32 + 32 + lane);
        unsigned ta1 = __ldg(tabL + b1 * 32 + lane);
        unsigned tb1 = __ldg(tabL + b1 * 32 + 32 + lane);
        unsigned xp0 = __ldg((const unsigned*)g_xb + (size_t)e0.x * 32 + lane);
        unsigned xp1 = __ldg((const unsigned*)g_xb + (size_t)e1.x * 32 + lane);
        float2 A0 = unpack_bf16x2(ta0), B0 = unpack_bf16x2(tb0), X0 = unpack_bf16x2(xp0);
        float2 A1 = unpack_bf16x2(ta1), B1 = unpack_bf16x2(tb1), X1 = unpack_bf16x2(xp1);
        float u0 = 1.0f - f0, u1 = 1.0f - f1;
        acc.x += (u0 * A0.x + f0 * B0.x) * X0.x;
        acc.y += (u0 * A0.y + f0 * B0.y) * X0.y;
        acc.x += (u1 * A1.x + f1 * B1.x) * X1.x;
        acc.y += (u1 * A1.y + f1 * B1.y) * X1.y;
    }
    if (k < end) {
        int2 e0 = __ldg(&g_cse[k]);
        int b0 = e0.y >> 16;
        float f0 = (float)(e0.y & 0xFFFF) * (1.0f / 65535.0f);
        unsigned ta0 = __ldg(tabL + b0 * 32 + lane);
        unsigned tb0 = __ldg(tabL + b0 * 32 + 32 + lane);
        unsigned xp0 = __ldg((const unsigned*)g_xb + (size_t)e0.x * 32 + lane);
        float2 A0 = unpack_bf16x2(ta0), B0 = unpack_bf16x2(tb0), X0 = unpack_bf16x2(xp0);
        float u0 = 1.0f - f0;
        acc.x += (u0 * A0.x + f0 * B0.x) * X0.x;
        acc.y += (u0 * A0.y + f0 * B0.y) * X0.y;
    }
    *(float2*)(g_agg + (size_t)node * Ff + lane * 2) = acc;
}

// ---------------- output ----------------
__global__ void zero_out(float* out) {
    if (threadIdx.x < NGg) out[threadIdx.x] = 0.0f;
}
__global__ void reduce_out(const int* __restrict__ batch, const float* __restrict__ ow2,
                           const float* __restrict__ ob2, float* __restrict__ out)
{
    int n = blockIdx.x * 256 + threadIdx.x;
    if (n >= Nn) return;
    const float4* hv = (const float4*)(g_t1 + (size_t)n * Ff);
    float s = 0.0f;
    #pragma unroll
    for (int j = 0; j < 16; j++) {
        float4 a = __ldg(hv + j);
        float4 w = __ldg((const float4*)ow2 + j);
        s += a.x * w.x + a.y * w.y + a.z * w.z + a.w * w.w;
    }
    atomicAdd(&out[__ldg(batch + n)], s + __ldg(ob2));
}

// ---------------- host ----------------
extern "C" void kernel_launch(void* const* d_in, const int* in_sizes, int n_in,
                              void* d_out, int out_size)
{
    const int*   z    = (const int*)  d_in[0];
    const float* pos  = (const float*)d_in[1];
    const int*   batch= (const int*)  d_in[2];
    const int*   ei   = (const int*)  d_in[3];
    const float* emb  = (const float*)d_in[4];
    const float* mw1  = (const float*)d_in[5];
    const float* mb1  = (const float*)d_in[6];
    const float* mw2  = (const float*)d_in[7];
    const float* mb2  = (const float*)d_in[8];
    const float* l1w  = (const float*)d_in[9];
    const float* l2w  = (const float*)d_in[10];
    const float* l2b  = (const float*)d_in[11];
    const float* lw   = (const float*)d_in[12];
    const float* lb   = (const float*)d_in[13];
    const float* ow1  = (const float*)d_in[14];
    const float* ob1  = (const float*)d_in[15];
    const float* ow2  = (const float*)d_in[16];
    const float* ob2  = (const float*)d_in[17];
    float* out = (float*)d_out;

    const int SMA = 256 * 36 * 4;
    const int SM64  = SMA + 32 * (64 + 8) * 4;
    const int SM128 = SMA + 32 * (128 + 8) * 4;
    cudaFuncSetAttribute(mma_gemm<0>, cudaFuncAttributeMaxDynamicSharedMemorySize, SM64);
    cudaFuncSetAttribute(mma_gemm<1>, cudaFuncAttributeMaxDynamicSharedMemorySize, SM128);
    cudaFuncSetAttribute(mma_gemm<2>, cudaFuncAttributeMaxDynamicSharedMemorySize, SM128);
    cudaFuncSetAttribute(mma_gemm<3>, cudaFuncAttributeMaxDynamicSharedMemorySize, SM64);

    init_h<<<Nn * Hh / 4 / 256, 256>>>(z, emb);
    zero_cnt<<<(Nn + 255) / 256, 256>>>();
    count_dst<<<(Ee + 255) / 256, 256>>>(ei);
    scan_a<<<NBLK, 256>>>();
    scan_b<<<1, 256>>>();
    scan_c<<<NBLK, 256>>>();
    edge_prep_fill<<<(Ee + 255) / 256, 256>>>(pos, ei);
    build_tab<<<dim3(BINS / 64, Ll), 256>>>(mw1, mb1, mw2, mb2);

    const int NBG = (Nn + 255) / 256;             // 196
    for (int i = 0; i < Ll; i++) {
        mma_gemm<0><<<NBG, 256, SM64>>>(l1w + i * Hh * Ff, nullptr);
        edge_agg<<<(Nn * 32 + 255) / 256, 256>>>(i);
        mma_gemm<1><<<NBG, 256, SM128>>>(l2w + i * Ff * Hh, l2b + i * Hh);
        mma_gemm<2><<<NBG, 256, SM128>>>(lw + i * Hh * Hh, lb + i * Hh);
    }
    zero_out<<<1, 256>>>(out);
    mma_gemm<3><<<NBG, 256, SM64>>>(ow1, ob1);
    reduce_out<<<(Nn + 255) / 256, 256>>>(batch, ow2, ob2, out);
}